// round 11
// baseline (speedup 1.0000x reference)
#include <cuda_runtime.h>

#define BATCH  32
#define NP     4096
#define NSLOT  64                // slot = w*32 + b; opposite cloud = s ^ 32
#define NBX    64
#define NBY    64
#define NB2    (NBX * NBY)       // 4096 bins
#define XMIN   (-5.0f)
#define W      0.15625f          // 10/64, exact in fp32
#define INVW   6.4f

// candidates binned by (x,y), y-minor; preprocessed: (-2x, -2y, -2z, ||c||^2)
__device__ float4         g_pts[NSLOT][NP];
__device__ unsigned short g_qid[NSLOT][NP];
__device__ int            g_bs[NSLOT][NB2 + 1];
__device__ float          g_dist[NSLOT][NP];   // by ORIGINAL index

static __device__ __forceinline__ int bco(float v) {
    int b = (int)floorf((v - XMIN) * INVW);
    return min(max(b, 0), NBX - 1);
}

// ---------------------------------------------------------------------------
// 1) per-slot counting sort by (x,y)-bin (+ preprocess). One block per slot.
// ---------------------------------------------------------------------------
__global__ void __launch_bounds__(512)
prep_kernel(const float* __restrict__ x1, const float* __restrict__ x2) {
    __shared__ int hist[NB2];
    __shared__ int cur[NB2];
    __shared__ int wsum[16];

    const int s = blockIdx.x;
    const int w = s >> 5, b = s & 31;
    const float* src = (w ? x2 : x1) + (size_t)b * NP * 3;
    const int tid = threadIdx.x;

    for (int i = tid; i < NB2; i += 512) hist[i] = 0;
    __syncthreads();

    for (int i = tid; i < NP; i += 512) {
        int bn = bco(src[3 * i]) * NBY + bco(src[3 * i + 1]);
        atomicAdd(&hist[bn], 1);
    }
    __syncthreads();

    // exclusive scan of 4096 bins: 512 threads x 8 bins each
    const int per = NB2 / 512;
    const int base = tid * per;
    int lsum = 0;
    #pragma unroll
    for (int i = 0; i < per; i++) lsum += hist[base + i];

    int lane = tid & 31, wid = tid >> 5;
    int v = lsum;
    #pragma unroll
    for (int o = 1; o < 32; o <<= 1) {
        int n = __shfl_up_sync(0xffffffffu, v, o);
        if (lane >= o) v += n;
    }
    if (lane == 31) wsum[wid] = v;
    __syncthreads();
    if (wid == 0) {
        int t = (lane < 16) ? wsum[lane] : 0;
        #pragma unroll
        for (int o = 1; o < 16; o <<= 1) {
            int n = __shfl_up_sync(0xffffffffu, t, o);
            if (lane >= o) t += n;
        }
        if (lane < 16) wsum[lane] = t;
    }
    __syncthreads();
    int run = (v - lsum) + (wid > 0 ? wsum[wid - 1] : 0);

    #pragma unroll
    for (int i = 0; i < per; i++) {
        int c = hist[base + i];
        g_bs[s][base + i] = run;
        cur[base + i] = run;
        run += c;
    }
    if (tid == 0) g_bs[s][NB2] = NP;
    __syncthreads();

    for (int i = tid; i < NP; i += 512) {
        float x = src[3 * i], y = src[3 * i + 1], z = src[3 * i + 2];
        int bn = bco(x) * NBY + bco(y);
        int pos = atomicAdd(&cur[bn], 1);
        g_pts[s][pos] = make_float4(-2.0f * x, -2.0f * y, -2.0f * z,
                                    x * x + y * y + z * z);
        g_qid[s][pos] = (unsigned short)i;
    }
}

// ---------------------------------------------------------------------------
// 2) query: warp-uniform expanding (x,y)-rect scan, broadcast candidate loads,
//    4 independent min accumulators. grid = (NP/256, NSLOT).
// ---------------------------------------------------------------------------
#define SCAN_RANGE(S, E)                                                        \
    {                                                                           \
        int _i = (S), _e = (E);                                                 \
        for (; _i + 4 <= _e; _i += 4) {                                         \
            float4 c0 = ptsc[_i],     c1 = ptsc[_i + 1];                        \
            float4 c2 = ptsc[_i + 2], c3 = ptsc[_i + 3];                        \
            m0 = fminf(m0, fmaf(qx, c0.x, fmaf(qy, c0.y, fmaf(qz, c0.z, c0.w)))); \
            m1 = fminf(m1, fmaf(qx, c1.x, fmaf(qy, c1.y, fmaf(qz, c1.z, c1.w)))); \
            m2 = fminf(m2, fmaf(qx, c2.x, fmaf(qy, c2.y, fmaf(qz, c2.z, c2.w)))); \
            m3 = fminf(m3, fmaf(qx, c3.x, fmaf(qy, c3.y, fmaf(qz, c3.z, c3.w)))); \
        }                                                                       \
        for (; _i < _e; _i++) {                                                 \
            float4 c0 = ptsc[_i];                                               \
            m0 = fminf(m0, fmaf(qx, c0.x, fmaf(qy, c0.y, fmaf(qz, c0.z, c0.w)))); \
        }                                                                       \
    }

__global__ void __launch_bounds__(256)
query_kernel() {
    const unsigned FULL = 0xffffffffu;
    const int sq = blockIdx.y;
    const int sc = sq ^ 32;                  // opposite cloud, same batch
    const int qi = blockIdx.x * 256 + threadIdx.x;

    const float4* __restrict__ ptsq = g_pts[sq];
    const float4* __restrict__ ptsc = g_pts[sc];
    const int*    __restrict__ bs   = g_bs[sc];

    float4 qp = ptsq[qi];
    const int qid = g_qid[sq][qi];
    const float qx = -0.5f * qp.x;           // exact inverse of -2x
    const float qy = -0.5f * qp.y;
    const float qz = -0.5f * qp.z;
    const float qq = qp.w;

    const int bx = bco(qx);
    const int by = bco(qy);
    int xlo = max(__reduce_min_sync(FULL, bx) - 1, 0);
    int xhi = min(__reduce_max_sync(FULL, bx) + 1, NBX - 1);
    int ylo = max(__reduce_min_sync(FULL, by) - 1, 0);
    int yhi = min(__reduce_max_sync(FULL, by) + 1, NBY - 1);

    const float INF = __int_as_float(0x7f800000);
    float m0 = INF, m1 = INF, m2 = INF, m3 = INF;

    // initial rectangle: each x-column is one contiguous run (y-minor order)
    for (int x = xlo; x <= xhi; x++)
        SCAN_RANGE(bs[x * NBY + ylo], bs[x * NBY + yhi + 1]);

    while (true) {
        float m = fminf(fminf(m0, m1), fminf(m2, m3));
        float el = (xlo == 0)       ? INF : qx - (XMIN + (float)xlo * W);
        float eh = (xhi == NBX - 1) ? INF : (XMIN + (float)(xhi + 1) * W) - qx;
        float fl = (ylo == 0)       ? INF : qy - (XMIN + (float)ylo * W);
        float fh = (yhi == NBY - 1) ? INF : (XMIN + (float)(yhi + 1) * W) - qy;
        float bnd = fminf(fminf(el, eh), fminf(fl, fh));
        bool done = (qq + m) <= bnd * bnd * 0.9999f;
        if (__all_sync(FULL, done)) break;
        if (xlo == 0 && xhi == NBX - 1 && ylo == 0 && yhi == NBY - 1) break;

        int nxlo = max(xlo - 1, 0), nxhi = min(xhi + 1, NBX - 1);
        int nylo = max(ylo - 1, 0), nyhi = min(yhi + 1, NBY - 1);
        if (nxlo < xlo)
            SCAN_RANGE(bs[nxlo * NBY + nylo], bs[nxlo * NBY + nyhi + 1]);
        if (nxhi > xhi)
            SCAN_RANGE(bs[nxhi * NBY + nylo], bs[nxhi * NBY + nyhi + 1]);
        for (int x = xlo; x <= xhi; x++) {
            if (nylo < ylo)
                SCAN_RANGE(bs[x * NBY + nylo], bs[x * NBY + ylo]);
            if (nyhi > yhi)
                SCAN_RANGE(bs[x * NBY + yhi + 1], bs[x * NBY + nyhi + 1]);
        }
        xlo = nxlo; xhi = nxhi; ylo = nylo; yhi = nyhi;
    }

    float m = fminf(fminf(m0, m1), fminf(m2, m3));
    g_dist[sq][qid] = qq + m;
}

// ---------------------------------------------------------------------------
// 3) deterministic fixed-order reduce: out[b] = (sum_d0 + sum_d1) / NP
// ---------------------------------------------------------------------------
__global__ void __launch_bounds__(256)
reduce_kernel(float* __restrict__ out) {
    const int b = blockIdx.x, tid = threadIdx.x;
    float s = 0.0f;
    #pragma unroll
    for (int d = 0; d < 2; d++)
        for (int i = tid; i < NP; i += 256)
            s += g_dist[d * BATCH + b][i];

    __shared__ float red[256];
    red[tid] = s;
    __syncthreads();
    #pragma unroll
    for (int o = 128; o > 0; o >>= 1) {
        if (tid < o) red[tid] += red[tid + o];
        __syncthreads();
    }
    if (tid == 0) out[b] = red[0] * (1.0f / (float)NP);
}

extern "C" void kernel_launch(void* const* d_in, const int* in_sizes, int n_in,
                              void* d_out, int out_size) {
    const float* x1 = (const float*)d_in[0];
    const float* x2 = (const float*)d_in[1];
    float* out = (float*)d_out;

    prep_kernel<<<NSLOT, 512>>>(x1, x2);
    query_kernel<<<dim3(NP / 256, NSLOT), 256>>>();
    reduce_kernel<<<BATCH, 256>>>(out);
}